// round 16
// baseline (speedup 1.0000x reference)
#include <cuda_runtime.h>

#define BATCH 1024
#define CF 10     // fields
#define CG 40     // channels = fields * 4 orientations

typedef unsigned long long ull;

// ---------------- packed f32x2 helpers ----------------
__device__ __forceinline__ ull splat2(float x) {
    ull d; asm("mov.b64 %0, {%1, %1};" : "=l"(d) : "f"(x)); return d;
}
__device__ __forceinline__ void ffma2(ull& d, ull a, ull b) {
    asm("fma.rn.f32x2 %0, %1, %2, %0;" : "+l"(d) : "l"(a), "l"(b));
}
__device__ __forceinline__ void unpack2(ull v, float& x, float& y) {
    asm("mov.b64 {%0, %1}, %2;" : "=f"(x), "=f"(y) : "l"(v));
}

// ---------------- device scratch (no allocations allowed) ----------------
__device__ float  g_bufA[BATCH * CG * 28 * 28];   // ~128 MB
__device__ float  g_bufB[BATCH * CG * 28 * 28];   // ~128 MB
__device__ float  g_part[2][4096 * 20];           // ping-pong per-CTA (sum, sumsq) float
__device__ float  g_wx[97960];                    // pre-expanded P4 kernels, all layers
__device__ float  g_scale[7][CF];                 // per-layer BN scale
__device__ float  g_shift[7][CF];                 // per-layer BN shift

// expanded-weight offsets (floats, all 16B aligned)
#define WOFF_L1 0
#define WOFF_W2 360
#define WOFF_W3 14760
#define WOFF_W4 29160
#define WOFF_W5 43560
#define WOFF_W6 57960
#define WOFF_W7 72360

// rot90^r (numpy counterclockwise) source index: rotated[y][x] = in[ry][rx]
__device__ __forceinline__ void rotsrc(int r, int y, int x, int n, int& ry, int& rx) {
    switch (r & 3) {
        case 0:  ry = y;         rx = x;         break;
        case 1:  ry = x;         rx = n - 1 - y; break;
        case 2:  ry = n - 1 - y; rx = n - 1 - x; break;
        default: ry = n - 1 - x; rx = y;         break;
    }
}

// ---------------- one-shot weight expansion ----------------
__global__ void expand_weights(const float* __restrict__ w1, const float* __restrict__ w2,
                               const float* __restrict__ w3, const float* __restrict__ w4,
                               const float* __restrict__ w5, const float* __restrict__ w6,
                               const float* __restrict__ w7) {
    int i = blockIdx.x * 256 + threadIdx.x;
    if (i < 360) {                       // lifting kernel: [ky][kx][co4]
        int co4 = i % 40; int t = i / 40; int kx = t % 3, ky = t / 3;
        int co = co4 >> 2, r = co4 & 3; int ry, rx; rotsrc(r, ky, kx, 3, ry, rx);
        g_wx[i] = w1[co * 9 + ry * 3 + rx];
    } else if (i < 72360) {              // 5 regular 3x3 layers: [ci4][ky][kx][co4]
        int j = i - 360;
        int layer = j / 14400; int k = j - layer * 14400;
        const float* w = layer == 0 ? w2 : layer == 1 ? w3 : layer == 2 ? w4
                       : layer == 3 ? w5 : w6;
        int co4 = k % 40; int t = k / 40; int kx = t % 3; t /= 3; int ky = t % 3; int ci4 = t / 3;
        int co = co4 >> 2, r = co4 & 3, ci = ci4 >> 2, s = ci4 & 3;
        int srel = (s - r + 4) & 3; int ry, rx; rotsrc(r, ky, kx, 3, ry, rx);
        g_wx[i] = w[((co * 10 + ci) * 4 + srel) * 9 + ry * 3 + rx];
    } else if (i < 97960) {              // 4x4 layer: [ci4][ky][kx][co4]
        int m = i - 72360;
        int co4 = m % 40; int t = m / 40; int kx = t % 4; t /= 4; int ky = t % 4; int ci4 = t / 4;
        int co = co4 >> 2, r = co4 & 3, ci = ci4 >> 2, s = ci4 & 3;
        int srel = (s - r + 4) & 3; int ry, rx; rotsrc(r, ky, kx, 4, ry, rx);
        g_wx[i] = w7[((co * 10 + ci) * 4 + srel) * 16 + ry * 4 + rx];
    }
}

// ---------------- per-layer BN finalize: partials -> global (scale, shift) -------------
__global__ void finalize_bn(int layer, int rp, int nblk, const float* __restrict__ gamma,
                            const float* __restrict__ beta, double invN) {
    int f = threadIdx.x >> 5, lane = threadIdx.x & 31;
    if (f >= CF) return;
    double s = 0.0, q = 0.0;
    const float* p = g_part[rp] + f * 2;
    for (int i = lane; i < nblk; i += 32) {
        float2 v = *(const float2*)(p + i * 20);
        s += (double)v.x; q += (double)v.y;
    }
    #pragma unroll
    for (int o = 16; o; o >>= 1) {
        s += __shfl_xor_sync(0xffffffffu, s, o);
        q += __shfl_xor_sync(0xffffffffu, q, o);
    }
    if (lane == 0) {
        double mean = s * invN;
        double var = q * invN - mean * mean;
        float sc = gamma[f] * (float)rsqrt(var + 1e-5);
        g_scale[layer][f] = sc;
        g_shift[layer][f] = beta[f] - (float)mean * sc;
    }
}

// Warp-cooperative stat flush, two adjacent fields (fast path when warp-uniform).
__device__ __forceinline__ void stat_flush2(int f0, float s0, float q0, float s1, float q1,
                                            double* sSum, double* sSq) {
    const unsigned FULL = 0xffffffffu;
    int f00 = __shfl_sync(FULL, f0, 0);
    if (__all_sync(FULL, f0 == f00)) {
        #pragma unroll
        for (int o = 16; o; o >>= 1) {
            s0 += __shfl_xor_sync(FULL, s0, o);
            q0 += __shfl_xor_sync(FULL, q0, o);
            s1 += __shfl_xor_sync(FULL, s1, o);
            q1 += __shfl_xor_sync(FULL, q1, o);
        }
        if ((threadIdx.x & 31) == 0) {
            atomicAdd(&sSum[f00],     (double)s0); atomicAdd(&sSq[f00],     (double)q0);
            atomicAdd(&sSum[f00 + 1], (double)s1); atomicAdd(&sSq[f00 + 1], (double)q1);
        }
    } else {
        atomicAdd(&sSum[f0],     (double)s0); atomicAdd(&sSq[f0],     (double)q0);
        atomicAdd(&sSum[f0 + 1], (double)s1); atomicAdd(&sSq[f0 + 1], (double)q1);
    }
}

// Single-field variant.
__device__ __forceinline__ void stat_flush1(int f0, float s0, float q0,
                                            double* sSum, double* sSq) {
    const unsigned FULL = 0xffffffffu;
    int f00 = __shfl_sync(FULL, f0, 0);
    if (__all_sync(FULL, f0 == f00)) {
        #pragma unroll
        for (int o = 16; o; o >>= 1) {
            s0 += __shfl_xor_sync(FULL, s0, o);
            q0 += __shfl_xor_sync(FULL, q0, o);
        }
        if ((threadIdx.x & 31) == 0) {
            atomicAdd(&sSum[f00], (double)s0); atomicAdd(&sSq[f00], (double)q0);
        }
    } else {
        atomicAdd(&sSum[f0], (double)s0); atomicAdd(&sSq[f0], (double)q0);
    }
}

// ---------------- layer 1: lifting conv (Cin=1, 3x3, pad 1) -> g_bufA, part[0]
__global__ __launch_bounds__(256) void lift_conv(const float* __restrict__ x) {
    __shared__ float sI[900];        // 30x30 padded
    __shared__ float sW[360];        // [ky][kx][co4]
    __shared__ double sSum[CF], sSq[CF];
    int tid = threadIdx.x, b = blockIdx.x;
    if (tid < CF) { sSum[tid] = 0.0; sSq[tid] = 0.0; }
    for (int i = tid; i < 900; i += 256) sI[i] = 0.f;
    __syncthreads();
    const float* xb = x + b * 784;
    for (int i4 = tid; i4 < 196; i4 += 256) {
        float4 v = *(const float4*)(xb + i4 * 4);
        int pos = i4 * 4; int y = pos / 28; int xx = pos - y * 28;
        float* d = sI + (y + 1) * 30 + xx + 1;
        d[0] = v.x; d[1] = v.y; d[2] = v.z; d[3] = v.w;
    }
    if (tid < 90) ((float4*)sW)[tid] = ((const float4*)(g_wx + WOFF_L1))[tid];
    __syncthreads();
    float* dst = g_bufA;
    for (int base = 0; base < 980; base += 256) {
        int item = base + tid; bool on = item < 980; int it = on ? item : 979;
        int chunk = it / 196; int strip = it - chunk * 196;
        int y = strip / 7; int x0 = (strip - y * 7) * 4; int cob = chunk * 8;
        float acc[8][4];
        #pragma unroll
        for (int n = 0; n < 8; n++)
            #pragma unroll
            for (int p = 0; p < 4; p++) acc[n][p] = 0.f;
        const float* Ir = sI + y * 30 + x0;
        #pragma unroll
        for (int ky = 0; ky < 3; ky++) {
            float inv[6];
            #pragma unroll
            for (int i = 0; i < 6; i++) inv[i] = Ir[ky * 30 + i];
            #pragma unroll
            for (int kx = 0; kx < 3; kx++) {
                const float* wp = sW + (ky * 3 + kx) * 40 + cob;
                #pragma unroll
                for (int n = 0; n < 8; n++) {
                    float wv = wp[n];
                    #pragma unroll
                    for (int p = 0; p < 4; p++) acc[n][p] = fmaf(inv[p + kx], wv, acc[n][p]);
                }
            }
        }
        float s0 = 0, q0 = 0, s1 = 0, q1 = 0;
        if (on) {
            #pragma unroll
            for (int n = 0; n < 8; n++) {
                float* op = dst + ((b * 40 + cob + n) * 28 + y) * 28 + x0;
                #pragma unroll
                for (int p = 0; p < 4; p++) {
                    float v = acc[n][p]; op[p] = v;
                    if (n < 4) { s0 += v; q0 += v * v; } else { s1 += v; q1 += v * v; }
                }
            }
        }
        stat_flush2(cob >> 2, s0, q0, s1, q1, sSum, sSq);
    }
    __syncthreads();
    if (tid < CF) {
        g_part[0][b * 20 + tid * 2]     = (float)sSum[tid];
        g_part[0][b * 20 + tid * 2 + 1] = (float)sSq[tid];
    }
}

// ---------------- layer 2: gconv 3x3 at 28x28, split 2 y-halves x 2 cout-halves --------
// FFMA2 version. Thread: 2 cout-pairs (4 couts) x 2 output rows x 4 px.
// Per ci: 9 weight-pair-vec loads cached in regs, 4 input rows splatted once.
__global__ __launch_bounds__(256, 2) void conv28(int inb, int outb, int woff,
                                                 int prev, int wpar) {
    extern __shared__ float sm[];
    float* sI = sm;            // 20480
    float* sW = sm + 20480;    // [ci4*3*3][20] = 7200
    __shared__ double sSum[CF], sSq[CF];
    __shared__ float sSc[CF], sSh[CF];
    int tid = threadIdx.x, bx = blockIdx.x;
    int b = bx >> 2, h = (bx >> 1) & 1, ch = bx & 1;
    if (tid < CF) {
        sSum[tid] = 0.0; sSq[tid] = 0.0;
        sSc[tid] = g_scale[prev][tid]; sSh[tid] = g_shift[prev][tid];
    }
    float4* z4 = (float4*)sI;
    for (int i = tid; i < 5120; i += 256) z4[i] = make_float4(0.f, 0.f, 0.f, 0.f);
    __syncthreads();
    const float* src = (inb ? g_bufB : g_bufA) + b * 31360;
    int gybase = h ? 13 : 0;
    int lybase = h ? 0 : 1;
    for (int i4 = tid; i4 < 4200; i4 += 256) {
        int c = i4 / 105; int rem = i4 - c * 105; int r = rem / 7; int xq = rem - r * 7;
        float4 v = *(const float4*)(src + (c * 28 + gybase + r) * 28 + xq * 4);
        int f = c >> 2; float sc = sSc[f], sh = sSh[f];
        float* d = sI + c * 512 + (lybase + r) * 32 + xq * 4 + 1;
        d[0] = fmaxf(fmaf(v.x, sc, sh), 0.f);
        d[1] = fmaxf(fmaf(v.y, sc, sh), 0.f);
        d[2] = fmaxf(fmaf(v.z, sc, sh), 0.f);
        d[3] = fmaxf(fmaf(v.w, sc, sh), 0.f);
    }
    for (int i4 = tid; i4 < 1800; i4 += 256) {
        int g = i4 / 5; int o4 = i4 - g * 5;
        *(float4*)(sW + g * 20 + o4 * 4) =
            *(const float4*)(g_wx + woff + g * 40 + ch * 20 + o4 * 4);
    }
    __syncthreads();
    float* dst = (outb ? g_bufB : g_bufA);
    {
        int it = tid < 245 ? tid : 244; bool on = tid < 245;
        int chunk = it / 49; int rest = it - chunk * 49;
        int yp = rest / 7; int xq = rest - yp * 7;
        int y0 = yp * 2; int x0 = xq * 4; int cob = chunk * 4;
        ull acc2[2][2][4];      // [copair][oy][px]
        #pragma unroll
        for (int n = 0; n < 2; n++)
            #pragma unroll
            for (int oy = 0; oy < 2; oy++)
                #pragma unroll
                for (int p = 0; p < 4; p++) acc2[n][oy][p] = 0ull;
        for (int ci = 0; ci < 40; ci++) {
            const float* Wp = sW + ci * 180 + cob;
            ull w2[9][2];
            #pragma unroll
            for (int k = 0; k < 9; k++) {
                ulonglong2 t = *(const ulonglong2*)(Wp + k * 20);
                w2[k][0] = t.x; w2[k][1] = t.y;
            }
            const float* Ir = sI + ci * 512 + y0 * 32 + x0;
            #pragma unroll
            for (int iy = 0; iy < 4; iy++) {
                float4 va = *(const float4*)(Ir + iy * 32);
                float2 vb = *(const float2*)(Ir + iy * 32 + 4);
                ull S[6];
                S[0] = splat2(va.x); S[1] = splat2(va.y); S[2] = splat2(va.z);
                S[3] = splat2(va.w); S[4] = splat2(vb.x); S[5] = splat2(vb.y);
                #pragma unroll
                for (int oy = 0; oy < 2; oy++) {
                    int ky = iy - oy;
                    if (ky < 0 || ky > 2) continue;
                    #pragma unroll
                    for (int kx = 0; kx < 3; kx++) {
                        ull wa = w2[ky * 3 + kx][0];
                        ull wb = w2[ky * 3 + kx][1];
                        #pragma unroll
                        for (int p = 0; p < 4; p++) {
                            ffma2(acc2[0][oy][p], S[p + kx], wa);
                            ffma2(acc2[1][oy][p], S[p + kx], wb);
                        }
                    }
                }
            }
        }
        float s0 = 0, q0 = 0;
        if (on) {
            #pragma unroll
            for (int n = 0; n < 2; n++)
                #pragma unroll
                for (int oy = 0; oy < 2; oy++) {
                    float lo[4], hi[4];
                    #pragma unroll
                    for (int p = 0; p < 4; p++) unpack2(acc2[n][oy][p], lo[p], hi[p]);
                    int gy = h * 14 + y0 + oy;
                    int co0 = ch * 20 + cob + 2 * n;
                    float4 o0, o1;
                    o0.x = lo[0]; o0.y = lo[1]; o0.z = lo[2]; o0.w = lo[3];
                    o1.x = hi[0]; o1.y = hi[1]; o1.z = hi[2]; o1.w = hi[3];
                    *(float4*)(dst + ((b * 40 + co0) * 28 + gy) * 28 + x0) = o0;
                    *(float4*)(dst + ((b * 40 + co0 + 1) * 28 + gy) * 28 + x0) = o1;
                    #pragma unroll
                    for (int p = 0; p < 4; p++) {
                        s0 += lo[p] + hi[p]; q0 += lo[p] * lo[p] + hi[p] * hi[p];
                    }
                }
        }
        stat_flush1(ch * 5 + chunk, s0, q0, sSum, sSq);
    }
    __syncthreads();
    if (tid < CF) {
        g_part[wpar][bx * 20 + tid * 2]     = (float)sSum[tid];
        g_part[wpar][bx * 20 + tid * 2 + 1] = (float)sSq[tid];
    }
}

// ---------------- layers 3-6: gconv 3x3 at 14x14 (optional fused 2x2 maxpool input) ----
// FFMA2: 1 cout-pair x 14 px per thread, 288 threads, 2 CTAs/SM.
template <bool POOL>
__global__ __launch_bounds__(288, 2) void conv14(int inb, int outb, int woff,
                                                 int prev, int wpar) {
    extern __shared__ float sm[];
    float* sI = sm;            // 12800
    float* sW = sm + 12800;    // 14400
    __shared__ double sSum[CF], sSq[CF];
    __shared__ float sSc[CF], sSh[CF];
    int tid = threadIdx.x, b = blockIdx.x, bd = blockDim.x;
    if (tid < CF) {
        sSum[tid] = 0.0; sSq[tid] = 0.0;
        sSc[tid] = g_scale[prev][tid]; sSh[tid] = g_shift[prev][tid];
    }
    float4* z4 = (float4*)sI;
    for (int i = tid; i < 3200; i += bd) z4[i] = make_float4(0.f, 0.f, 0.f, 0.f);
    __syncthreads();
    const float* srcbuf = (inb ? g_bufB : g_bufA);
    if (POOL) {
        for (int i = tid; i < 7840; i += bd) {
            int c = i / 196; int rem = i - c * 196; int py = rem / 14; int px = rem - py * 14;
            int f = c >> 2; float sc = sSc[f], sh = sSh[f];
            const float2* p0 = (const float2*)(srcbuf + b * 31360 + c * 784 + (py * 2) * 28 + px * 2);
            float2 u = p0[0], d = p0[14];
            float a0 = fmaxf(fmaf(u.x, sc, sh), 0.f);
            float a1 = fmaxf(fmaf(u.y, sc, sh), 0.f);
            float a2 = fmaxf(fmaf(d.x, sc, sh), 0.f);
            float a3 = fmaxf(fmaf(d.y, sc, sh), 0.f);
            sI[c * 320 + (py + 1) * 20 + px + 1] = fmaxf(fmaxf(a0, a1), fmaxf(a2, a3));
        }
    } else {
        for (int i4 = tid; i4 < 1960; i4 += bd) {
            int c = i4 / 49; int rem = i4 - c * 49;
            float4 v = *(const float4*)(srcbuf + b * 7840 + i4 * 4);
            int pos = rem * 4; int py = pos / 14; int px = pos - py * 14;
            int f = c >> 2; float sc = sSc[f], sh = sSh[f];
            float vv[4] = {v.x, v.y, v.z, v.w};
            float* base = sI + c * 320;
            #pragma unroll
            for (int j = 0; j < 4; j++) {
                base[(py + 1) * 20 + px + 1] = fmaxf(fmaf(vv[j], sc, sh), 0.f);
                if (++px == 14) { px = 0; py++; }
            }
        }
    }
    {
        const float4* wsrc = (const float4*)(g_wx + woff);
        float4* wdst = (float4*)sW;
        for (int i = tid; i < 3600; i += bd) wdst[i] = wsrc[i];
    }
    __syncthreads();
    float* dst = (outb ? g_bufB : g_bufA);
    {
        int item = tid; bool on = item < 280; int it = on ? item : 279;
        int chunk = it / 14; int y = it - chunk * 14; int cob = chunk * 2;
        ull acc2[14];
        #pragma unroll
        for (int p = 0; p < 14; p++) acc2[p] = 0ull;
        for (int ci = 0; ci < 40; ci++) {
            const float* Ir = sI + ci * 320 + y * 20;
            const float* wp = sW + ci * 360 + cob;
            #pragma unroll
            for (int ky = 0; ky < 3; ky++) {
                float4 v0 = *(const float4*)(Ir + ky * 20);
                float4 v1 = *(const float4*)(Ir + ky * 20 + 4);
                float4 v2 = *(const float4*)(Ir + ky * 20 + 8);
                float4 v3 = *(const float4*)(Ir + ky * 20 + 12);
                ull S[16];
                S[0]  = splat2(v0.x); S[1]  = splat2(v0.y); S[2]  = splat2(v0.z); S[3]  = splat2(v0.w);
                S[4]  = splat2(v1.x); S[5]  = splat2(v1.y); S[6]  = splat2(v1.z); S[7]  = splat2(v1.w);
                S[8]  = splat2(v2.x); S[9]  = splat2(v2.y); S[10] = splat2(v2.z); S[11] = splat2(v2.w);
                S[12] = splat2(v3.x); S[13] = splat2(v3.y); S[14] = splat2(v3.z); S[15] = splat2(v3.w);
                #pragma unroll
                for (int kx = 0; kx < 3; kx++) {
                    ull wv = *(const ull*)(wp + (ky * 3 + kx) * 40);
                    #pragma unroll
                    for (int p = 0; p < 14; p++) ffma2(acc2[p], S[p + kx], wv);
                }
            }
        }
        float s0 = 0, q0 = 0;
        if (on) {
            float* op0 = dst + ((b * 40 + cob) * 14 + y) * 14;
            float* op1 = op0 + 196;
            #pragma unroll
            for (int p = 0; p < 14; p++) {
                float a, bb; unpack2(acc2[p], a, bb);
                op0[p] = a; op1[p] = bb;
                s0 += a + bb; q0 += a * a + bb * bb;
            }
        }
        stat_flush1(chunk >> 1, s0, q0, sSum, sSq);
    }
    __syncthreads();
    if (tid < CF) {
        g_part[wpar][b * 20 + tid * 2]     = (float)sSum[tid];
        g_part[wpar][b * 20 + tid * 2 + 1] = (float)sSq[tid];
    }
}

// ---------------- layer 7: gconv 4x4, VALID, 14->11, two images per CTA ----------------
// FFMA2: 1 cout-pair x 11 px per thread, 448 threads.
__global__ __launch_bounds__(448) void conv4k(int inb, int outb, int woff,
                                              int prev, int wpar) {
    extern __shared__ float sm[];
    float* sI = sm;            // 22400
    float* sW = sm + 22400;    // 25600
    __shared__ double sSum[CF], sSq[CF];
    __shared__ float sSc[CF], sSh[CF];
    int tid = threadIdx.x, bd = blockDim.x;
    int b0 = blockIdx.x * 2;
    if (tid < CF) {
        sSum[tid] = 0.0; sSq[tid] = 0.0;
        sSc[tid] = g_scale[prev][tid]; sSh[tid] = g_shift[prev][tid];
    }
    __syncthreads();
    const float* srcbuf = (inb ? g_bufB : g_bufA);
    for (int i4 = tid; i4 < 3920; i4 += bd) {
        int img = i4 / 1960; int j4 = i4 - img * 1960;
        int c = j4 / 49; int rem = j4 - c * 49;
        float4 v = *(const float4*)(srcbuf + (b0 + img) * 7840 + j4 * 4);
        int pos = rem * 4; int py = pos / 14; int px = pos - py * 14;
        int f = c >> 2; float sc = sSc[f], sh = sSh[f];
        float vv[4] = {v.x, v.y, v.z, v.w};
        float* base = sI + (img * 40 + c) * 280;
        #pragma unroll
        for (int j = 0; j < 4; j++) {
            base[py * 20 + px] = fmaxf(fmaf(vv[j], sc, sh), 0.f);
            if (++px == 14) { px = 0; py++; }
        }
    }
    {
        const float4* wsrc = (const float4*)(g_wx + woff);
        float4* wdst = (float4*)sW;
        for (int i = tid; i < 6400; i += bd) wdst[i] = wsrc[i];
    }
    __syncthreads();
    float* dst = (outb ? g_bufB : g_bufA);
    {
        int item = tid; bool on = item < 440; int it = on ? item : 439;
        int img = it / 220; int rest = it - img * 220;
        int chunk = rest / 11; int y = rest - chunk * 11; int cob = chunk * 2;
        ull acc2[11];
        #pragma unroll
        for (int p = 0; p < 11; p++) acc2[p] = 0ull;
        for (int ci = 0; ci < 40; ci++) {
            const float* Ir = sI + (img * 40 + ci) * 280 + y * 20;
            const float* wp = sW + ci * 640 + cob;
            #pragma unroll
            for (int ky = 0; ky < 4; ky++) {
                float4 v0 = *(const float4*)(Ir + ky * 20);
                float4 v1 = *(const float4*)(Ir + ky * 20 + 4);
                float4 v2 = *(const float4*)(Ir + ky * 20 + 8);
                float2 v3 = *(const float2*)(Ir + ky * 20 + 12);
                ull S[14];
                S[0]  = splat2(v0.x); S[1]  = splat2(v0.y); S[2]  = splat2(v0.z); S[3]  = splat2(v0.w);
                S[4]  = splat2(v1.x); S[5]  = splat2(v1.y); S[6]  = splat2(v1.z); S[7]  = splat2(v1.w);
                S[8]  = splat2(v2.x); S[9]  = splat2(v2.y); S[10] = splat2(v2.z); S[11] = splat2(v2.w);
                S[12] = splat2(v3.x); S[13] = splat2(v3.y);
                #pragma unroll
                for (int kx = 0; kx < 4; kx++) {
                    ull wv = *(const ull*)(wp + (ky * 4 + kx) * 40);
                    #pragma unroll
                    for (int p = 0; p < 11; p++) ffma2(acc2[p], S[p + kx], wv);
                }
            }
        }
        float s0 = 0, q0 = 0;
        if (on) {
            float* op0 = dst + (((b0 + img) * 40 + cob) * 11 + y) * 11;
            float* op1 = op0 + 121;
            #pragma unroll
            for (int p = 0; p < 11; p++) {
                float a, bb; unpack2(acc2[p], a, bb);
                op0[p] = a; op1[p] = bb;
                s0 += a + bb; q0 += a * a + bb * bb;
            }
        }
        stat_flush1(chunk >> 1, s0, q0, sSum, sSq);
    }
    __syncthreads();
    if (tid < CF) {
        g_part[wpar][blockIdx.x * 20 + tid * 2]     = (float)sSum[tid];
        g_part[wpar][blockIdx.x * 20 + tid * 2 + 1] = (float)sSq[tid];
    }
}

// ---------------- act7 + orientation max + FC ----------------
__global__ __launch_bounds__(128) void fc_kernel(int inb, const float* __restrict__ wfc,
                                                 const float* __restrict__ bfc,
                                                 float* __restrict__ out, int prev) {
    __shared__ float sWf[12100];
    __shared__ float sOut[10];
    __shared__ float sSc[CF], sSh[CF];
    int tid = threadIdx.x, b = blockIdx.x;
    if (tid < 10) {
        sOut[tid] = bfc[tid];
        sSc[tid] = g_scale[prev][tid]; sSh[tid] = g_shift[prev][tid];
    }
    for (int i = tid; i < 12100; i += 128) sWf[i] = wfc[i];
    __syncthreads();
    const float* src = (inb ? g_bufB : g_bufA) + b * 4840;
    float acc[10];
    #pragma unroll
    for (int j = 0; j < 10; j++) acc[j] = 0.f;
    for (int idx = tid; idx < 1210; idx += 128) {
        int c = idx / 121; int p = idx - c * 121;
        const float* ip = src + c * 484 + p;
        float sc = sSc[c], sh = sSh[c];
        float a0 = fmaxf(fmaf(ip[0],   sc, sh), 0.f);
        float a1 = fmaxf(fmaf(ip[121], sc, sh), 0.f);
        float a2 = fmaxf(fmaf(ip[242], sc, sh), 0.f);
        float a3 = fmaxf(fmaf(ip[363], sc, sh), 0.f);
        float m = fmaxf(fmaxf(a0, a1), fmaxf(a2, a3));
        #pragma unroll
        for (int j = 0; j < 10; j++) acc[j] = fmaf(m, sWf[j * 1210 + idx], acc[j]);
    }
    #pragma unroll
    for (int j = 0; j < 10; j++) atomicAdd(&sOut[j], acc[j]);
    __syncthreads();
    if (tid < 10) out[b * 10 + tid] = sOut[tid];
}

// ---------------- launch ----------------
extern "C" void kernel_launch(void* const* d_in, const int* in_sizes, int n_in,
                              void* d_out, int out_size) {
    const float* x   = (const float*)d_in[0];
    const float* w1  = (const float*)d_in[1];
    const float* w2  = (const float*)d_in[2];
    const float* w3  = (const float*)d_in[3];
    const float* w4  = (const float*)d_in[4];
    const float* w5  = (const float*)d_in[5];
    const float* w6  = (const float*)d_in[6];
    const float* w7  = (const float*)d_in[7];
    const float* g1  = (const float*)d_in[8];
    const float* b1  = (const float*)d_in[9];
    const float* g2  = (const float*)d_in[10];
    const float* b2  = (const float*)d_in[11];
    const float* gs  = (const float*)d_in[12];
    const float* bs  = (const float*)d_in[13];
    const float* wfc = (const float*)d_in[14];
    const float* bfc = (const float*)d_in[15];
    float* out = (float*)d_out;

    const int SMEM28 = (20480 + 7200) * 4;    // 110720
    const int SMEM14 = (12800 + 14400) * 4;   // 108800
    const int SMEM4  = (22400 + 25600) * 4;   // 192000
    cudaFuncSetAttribute(conv28,        cudaFuncAttributeMaxDynamicSharedMemorySize, SMEM28);
    cudaFuncSetAttribute(conv14<true>,  cudaFuncAttributeMaxDynamicSharedMemorySize, SMEM14);
    cudaFuncSetAttribute(conv14<false>, cudaFuncAttributeMaxDynamicSharedMemorySize, SMEM14);
    cudaFuncSetAttribute(conv4k,        cudaFuncAttributeMaxDynamicSharedMemorySize, SMEM4);

    const double iN28 = 1.0 / (1024.0 * 4.0 * 784.0);
    const double iN14 = 1.0 / (1024.0 * 4.0 * 196.0);
    const double iN11 = 1.0 / (1024.0 * 4.0 * 121.0);

    expand_weights<<<383, 256>>>(w1, w2, w3, w4, w5, w6, w7);

    // layer L writes g_part[L & 1]; finalize_bn(L) reduces it into g_scale/g_shift[L]
    lift_conv<<<1024, 256>>>(x);                                    // -> A, part[0] (1024)
    finalize_bn<<<1, 320>>>(0, 0, 1024, g1, b1, iN28);
    conv28<<<4096, 256, SMEM28>>>(0, 1, WOFF_W2, 0, 1);             // A->B, part[1] (4096)
    finalize_bn<<<1, 320>>>(1, 1, 4096, g2, b2, iN28);
    conv14<true><<<1024, 288, SMEM14>>>(1, 0, WOFF_W3, 1, 0);       // pool(B)->A, part[0] (1024)
    finalize_bn<<<1, 320>>>(2, 0, 1024, gs, bs, iN14);
    conv14<false><<<1024, 288, SMEM14>>>(0, 1, WOFF_W4, 2, 1);      // A->B, part[1]
    finalize_bn<<<1, 320>>>(3, 1, 1024, gs, bs, iN14);
    conv14<false><<<1024, 288, SMEM14>>>(1, 0, WOFF_W5, 3, 0);      // B->A, part[0]
    finalize_bn<<<1, 320>>>(4, 0, 1024, gs, bs, iN14);
    conv14<false><<<1024, 288, SMEM14>>>(0, 1, WOFF_W6, 4, 1);      // A->B, part[1]
    finalize_bn<<<1, 320>>>(5, 1, 1024, gs, bs, iN14);
    conv4k<<<512, 448, SMEM4>>>(1, 0, WOFF_W7, 5, 0);               // B->A (11x11), part[0] (512)
    finalize_bn<<<1, 320>>>(6, 0, 512, gs, bs, iN11);
    fc_kernel<<<1024, 128>>>(0, wfc, bfc, out, 6);                  // A -> out
}

// round 17
// speedup vs baseline: 1.0004x; 1.0004x over previous
#include <cuda_runtime.h>

#define BATCH 1024
#define CF 10     // fields
#define CG 40     // channels = fields * 4 orientations

typedef unsigned long long ull;

// ---------------- packed f32x2 helpers ----------------
__device__ __forceinline__ ull splat2(float x) {
    ull d; asm("mov.b64 %0, {%1, %1};" : "=l"(d) : "f"(x)); return d;
}
__device__ __forceinline__ void ffma2(ull& d, ull a, ull b) {
    asm("fma.rn.f32x2 %0, %1, %2, %0;" : "+l"(d) : "l"(a), "l"(b));
}
__device__ __forceinline__ void unpack2(ull v, float& x, float& y) {
    asm("mov.b64 {%0, %1}, %2;" : "=f"(x), "=f"(y) : "l"(v));
}

// ---------------- device scratch (no allocations allowed) ----------------
__device__ float  g_bufA[BATCH * CG * 28 * 28];   // ~128 MB
__device__ float  g_bufB[BATCH * CG * 28 * 28];   // ~128 MB
__device__ float  g_part[2][4096 * 20];           // ping-pong per-CTA (sum, sumsq) float
__device__ float  g_wx[97960];                    // pre-expanded P4 kernels, all layers
__device__ float  g_scale[7][CF];                 // per-layer BN scale
__device__ float  g_shift[7][CF];                 // per-layer BN shift

// expanded-weight offsets (floats, all 16B aligned)
#define WOFF_L1 0
#define WOFF_W2 360
#define WOFF_W3 14760
#define WOFF_W4 29160
#define WOFF_W5 43560
#define WOFF_W6 57960
#define WOFF_W7 72360

// rot90^r (numpy counterclockwise) source index: rotated[y][x] = in[ry][rx]
__device__ __forceinline__ void rotsrc(int r, int y, int x, int n, int& ry, int& rx) {
    switch (r & 3) {
        case 0:  ry = y;         rx = x;         break;
        case 1:  ry = x;         rx = n - 1 - y; break;
        case 2:  ry = n - 1 - y; rx = n - 1 - x; break;
        default: ry = n - 1 - x; rx = y;         break;
    }
}

// ---------------- one-shot weight expansion ----------------
__global__ void expand_weights(const float* __restrict__ w1, const float* __restrict__ w2,
                               const float* __restrict__ w3, const float* __restrict__ w4,
                               const float* __restrict__ w5, const float* __restrict__ w6,
                               const float* __restrict__ w7) {
    int i = blockIdx.x * 256 + threadIdx.x;
    if (i < 360) {                       // lifting kernel: [ky][kx][co4]
        int co4 = i % 40; int t = i / 40; int kx = t % 3, ky = t / 3;
        int co = co4 >> 2, r = co4 & 3; int ry, rx; rotsrc(r, ky, kx, 3, ry, rx);
        g_wx[i] = w1[co * 9 + ry * 3 + rx];
    } else if (i < 72360) {              // 5 regular 3x3 layers: [ci4][ky][kx][co4]
        int j = i - 360;
        int layer = j / 14400; int k = j - layer * 14400;
        const float* w = layer == 0 ? w2 : layer == 1 ? w3 : layer == 2 ? w4
                       : layer == 3 ? w5 : w6;
        int co4 = k % 40; int t = k / 40; int kx = t % 3; t /= 3; int ky = t % 3; int ci4 = t / 3;
        int co = co4 >> 2, r = co4 & 3, ci = ci4 >> 2, s = ci4 & 3;
        int srel = (s - r + 4) & 3; int ry, rx; rotsrc(r, ky, kx, 3, ry, rx);
        g_wx[i] = w[((co * 10 + ci) * 4 + srel) * 9 + ry * 3 + rx];
    } else if (i < 97960) {              // 4x4 layer: [ci4][ky][kx][co4]
        int m = i - 72360;
        int co4 = m % 40; int t = m / 40; int kx = t % 4; t /= 4; int ky = t % 4; int ci4 = t / 4;
        int co = co4 >> 2, r = co4 & 3, ci = ci4 >> 2, s = ci4 & 3;
        int srel = (s - r + 4) & 3; int ry, rx; rotsrc(r, ky, kx, 4, ry, rx);
        g_wx[i] = w7[((co * 10 + ci) * 4 + srel) * 16 + ry * 4 + rx];
    }
}

// ---------------- per-layer BN finalize: partials -> global (scale, shift) -------------
__global__ void finalize_bn(int layer, int rp, int nblk, const float* __restrict__ gamma,
                            const float* __restrict__ beta, double invN) {
    int f = threadIdx.x >> 5, lane = threadIdx.x & 31;
    if (f >= CF) return;
    double s = 0.0, q = 0.0;
    const float* p = g_part[rp] + f * 2;
    for (int i = lane; i < nblk; i += 32) {
        float2 v = *(const float2*)(p + i * 20);
        s += (double)v.x; q += (double)v.y;
    }
    #pragma unroll
    for (int o = 16; o; o >>= 1) {
        s += __shfl_xor_sync(0xffffffffu, s, o);
        q += __shfl_xor_sync(0xffffffffu, q, o);
    }
    if (lane == 0) {
        double mean = s * invN;
        double var = q * invN - mean * mean;
        float sc = gamma[f] * (float)rsqrt(var + 1e-5);
        g_scale[layer][f] = sc;
        g_shift[layer][f] = beta[f] - (float)mean * sc;
    }
}

// Warp-cooperative stat flush, two adjacent fields (fast path when warp-uniform).
__device__ __forceinline__ void stat_flush2(int f0, float s0, float q0, float s1, float q1,
                                            double* sSum, double* sSq) {
    const unsigned FULL = 0xffffffffu;
    int f00 = __shfl_sync(FULL, f0, 0);
    if (__all_sync(FULL, f0 == f00)) {
        #pragma unroll
        for (int o = 16; o; o >>= 1) {
            s0 += __shfl_xor_sync(FULL, s0, o);
            q0 += __shfl_xor_sync(FULL, q0, o);
            s1 += __shfl_xor_sync(FULL, s1, o);
            q1 += __shfl_xor_sync(FULL, q1, o);
        }
        if ((threadIdx.x & 31) == 0) {
            atomicAdd(&sSum[f00],     (double)s0); atomicAdd(&sSq[f00],     (double)q0);
            atomicAdd(&sSum[f00 + 1], (double)s1); atomicAdd(&sSq[f00 + 1], (double)q1);
        }
    } else {
        atomicAdd(&sSum[f0],     (double)s0); atomicAdd(&sSq[f0],     (double)q0);
        atomicAdd(&sSum[f0 + 1], (double)s1); atomicAdd(&sSq[f0 + 1], (double)q1);
    }
}

// Single-field variant.
__device__ __forceinline__ void stat_flush1(int f0, float s0, float q0,
                                            double* sSum, double* sSq) {
    const unsigned FULL = 0xffffffffu;
    int f00 = __shfl_sync(FULL, f0, 0);
    if (__all_sync(FULL, f0 == f00)) {
        #pragma unroll
        for (int o = 16; o; o >>= 1) {
            s0 += __shfl_xor_sync(FULL, s0, o);
            q0 += __shfl_xor_sync(FULL, q0, o);
        }
        if ((threadIdx.x & 31) == 0) {
            atomicAdd(&sSum[f00], (double)s0); atomicAdd(&sSq[f00], (double)q0);
        }
    } else {
        atomicAdd(&sSum[f0], (double)s0); atomicAdd(&sSq[f0], (double)q0);
    }
}

// ---------------- layer 1: lifting conv (Cin=1, 3x3, pad 1) -> g_bufA, part[0]
__global__ __launch_bounds__(256) void lift_conv(const float* __restrict__ x) {
    __shared__ float sI[900];        // 30x30 padded
    __shared__ float sW[360];        // [ky][kx][co4]
    __shared__ double sSum[CF], sSq[CF];
    int tid = threadIdx.x, b = blockIdx.x;
    if (tid < CF) { sSum[tid] = 0.0; sSq[tid] = 0.0; }
    for (int i = tid; i < 900; i += 256) sI[i] = 0.f;
    __syncthreads();
    const float* xb = x + b * 784;
    for (int i4 = tid; i4 < 196; i4 += 256) {
        float4 v = *(const float4*)(xb + i4 * 4);
        int pos = i4 * 4; int y = pos / 28; int xx = pos - y * 28;
        float* d = sI + (y + 1) * 30 + xx + 1;
        d[0] = v.x; d[1] = v.y; d[2] = v.z; d[3] = v.w;
    }
    if (tid < 90) ((float4*)sW)[tid] = ((const float4*)(g_wx + WOFF_L1))[tid];
    __syncthreads();
    float* dst = g_bufA;
    for (int base = 0; base < 980; base += 256) {
        int item = base + tid; bool on = item < 980; int it = on ? item : 979;
        int chunk = it / 196; int strip = it - chunk * 196;
        int y = strip / 7; int x0 = (strip - y * 7) * 4; int cob = chunk * 8;
        float acc[8][4];
        #pragma unroll
        for (int n = 0; n < 8; n++)
            #pragma unroll
            for (int p = 0; p < 4; p++) acc[n][p] = 0.f;
        const float* Ir = sI + y * 30 + x0;
        #pragma unroll
        for (int ky = 0; ky < 3; ky++) {
            float inv[6];
            #pragma unroll
            for (int i = 0; i < 6; i++) inv[i] = Ir[ky * 30 + i];
            #pragma unroll
            for (int kx = 0; kx < 3; kx++) {
                const float* wp = sW + (ky * 3 + kx) * 40 + cob;
                #pragma unroll
                for (int n = 0; n < 8; n++) {
                    float wv = wp[n];
                    #pragma unroll
                    for (int p = 0; p < 4; p++) acc[n][p] = fmaf(inv[p + kx], wv, acc[n][p]);
                }
            }
        }
        float s0 = 0, q0 = 0, s1 = 0, q1 = 0;
        if (on) {
            #pragma unroll
            for (int n = 0; n < 8; n++) {
                float* op = dst + ((b * 40 + cob + n) * 28 + y) * 28 + x0;
                #pragma unroll
                for (int p = 0; p < 4; p++) {
                    float v = acc[n][p]; op[p] = v;
                    if (n < 4) { s0 += v; q0 += v * v; } else { s1 += v; q1 += v * v; }
                }
            }
        }
        stat_flush2(cob >> 2, s0, q0, s1, q1, sSum, sSq);
    }
    __syncthreads();
    if (tid < CF) {
        g_part[0][b * 20 + tid * 2]     = (float)sSum[tid];
        g_part[0][b * 20 + tid * 2 + 1] = (float)sSq[tid];
    }
}

// ---------------- layer 2: gconv 3x3 at 28x28, split 2 y-halves x 2 cout-halves --------
// FFMA2 version. Thread: 2 cout-pairs (4 couts) x 2 output rows x 4 px.
// Per ci: 9 weight-pair-vec loads cached in regs, 4 input rows splatted once.
__global__ __launch_bounds__(256, 2) void conv28(int inb, int outb, int woff,
                                                 int prev, int wpar) {
    extern __shared__ float sm[];
    float* sI = sm;            // 20480
    float* sW = sm + 20480;    // [ci4*3*3][20] = 7200
    __shared__ double sSum[CF], sSq[CF];
    __shared__ float sSc[CF], sSh[CF];
    int tid = threadIdx.x, bx = blockIdx.x;
    int b = bx >> 2, h = (bx >> 1) & 1, ch = bx & 1;
    if (tid < CF) {
        sSum[tid] = 0.0; sSq[tid] = 0.0;
        sSc[tid] = g_scale[prev][tid]; sSh[tid] = g_shift[prev][tid];
    }
    float4* z4 = (float4*)sI;
    for (int i = tid; i < 5120; i += 256) z4[i] = make_float4(0.f, 0.f, 0.f, 0.f);
    __syncthreads();
    const float* src = (inb ? g_bufB : g_bufA) + b * 31360;
    int gybase = h ? 13 : 0;
    int lybase = h ? 0 : 1;
    for (int i4 = tid; i4 < 4200; i4 += 256) {
        int c = i4 / 105; int rem = i4 - c * 105; int r = rem / 7; int xq = rem - r * 7;
        float4 v = *(const float4*)(src + (c * 28 + gybase + r) * 28 + xq * 4);
        int f = c >> 2; float sc = sSc[f], sh = sSh[f];
        float* d = sI + c * 512 + (lybase + r) * 32 + xq * 4 + 1;
        d[0] = fmaxf(fmaf(v.x, sc, sh), 0.f);
        d[1] = fmaxf(fmaf(v.y, sc, sh), 0.f);
        d[2] = fmaxf(fmaf(v.z, sc, sh), 0.f);
        d[3] = fmaxf(fmaf(v.w, sc, sh), 0.f);
    }
    for (int i4 = tid; i4 < 1800; i4 += 256) {
        int g = i4 / 5; int o4 = i4 - g * 5;
        *(float4*)(sW + g * 20 + o4 * 4) =
            *(const float4*)(g_wx + woff + g * 40 + ch * 20 + o4 * 4);
    }
    __syncthreads();
    float* dst = (outb ? g_bufB : g_bufA);
    {
        int it = tid < 245 ? tid : 244; bool on = tid < 245;
        int chunk = it / 49; int rest = it - chunk * 49;
        int yp = rest / 7; int xq = rest - yp * 7;
        int y0 = yp * 2; int x0 = xq * 4; int cob = chunk * 4;
        ull acc2[2][2][4];      // [copair][oy][px]
        #pragma unroll
        for (int n = 0; n < 2; n++)
            #pragma unroll
            for (int oy = 0; oy < 2; oy++)
                #pragma unroll
                for (int p = 0; p < 4; p++) acc2[n][oy][p] = 0ull;
        for (int ci = 0; ci < 40; ci++) {
            const float* Wp = sW + ci * 180 + cob;
            ull w2[9][2];
            #pragma unroll
            for (int k = 0; k < 9; k++) {
                ulonglong2 t = *(const ulonglong2*)(Wp + k * 20);
                w2[k][0] = t.x; w2[k][1] = t.y;
            }
            const float* Ir = sI + ci * 512 + y0 * 32 + x0;
            #pragma unroll
            for (int iy = 0; iy < 4; iy++) {
                float4 va = *(const float4*)(Ir + iy * 32);
                float2 vb = *(const float2*)(Ir + iy * 32 + 4);
                ull S[6];
                S[0] = splat2(va.x); S[1] = splat2(va.y); S[2] = splat2(va.z);
                S[3] = splat2(va.w); S[4] = splat2(vb.x); S[5] = splat2(vb.y);
                #pragma unroll
                for (int oy = 0; oy < 2; oy++) {
                    int ky = iy - oy;
                    if (ky < 0 || ky > 2) continue;
                    #pragma unroll
                    for (int kx = 0; kx < 3; kx++) {
                        ull wa = w2[ky * 3 + kx][0];
                        ull wb = w2[ky * 3 + kx][1];
                        #pragma unroll
                        for (int p = 0; p < 4; p++) {
                            ffma2(acc2[0][oy][p], S[p + kx], wa);
                            ffma2(acc2[1][oy][p], S[p + kx], wb);
                        }
                    }
                }
            }
        }
        float s0 = 0, q0 = 0;
        if (on) {
            #pragma unroll
            for (int n = 0; n < 2; n++)
                #pragma unroll
                for (int oy = 0; oy < 2; oy++) {
                    float lo[4], hi[4];
                    #pragma unroll
                    for (int p = 0; p < 4; p++) unpack2(acc2[n][oy][p], lo[p], hi[p]);
                    int gy = h * 14 + y0 + oy;
                    int co0 = ch * 20 + cob + 2 * n;
                    float4 o0, o1;
                    o0.x = lo[0]; o0.y = lo[1]; o0.z = lo[2]; o0.w = lo[3];
                    o1.x = hi[0]; o1.y = hi[1]; o1.z = hi[2]; o1.w = hi[3];
                    *(float4*)(dst + ((b * 40 + co0) * 28 + gy) * 28 + x0) = o0;
                    *(float4*)(dst + ((b * 40 + co0 + 1) * 28 + gy) * 28 + x0) = o1;
                    #pragma unroll
                    for (int p = 0; p < 4; p++) {
                        s0 += lo[p] + hi[p]; q0 += lo[p] * lo[p] + hi[p] * hi[p];
                    }
                }
        }
        stat_flush1(ch * 5 + chunk, s0, q0, sSum, sSq);
    }
    __syncthreads();
    if (tid < CF) {
        g_part[wpar][bx * 20 + tid * 2]     = (float)sSum[tid];
        g_part[wpar][bx * 20 + tid * 2 + 1] = (float)sSq[tid];
    }
}

// ---------------- layers 3-6: gconv 3x3 at 14x14 (optional fused 2x2 maxpool input) ----
// FFMA2: 1 cout-pair x 14 px per thread, 288 threads, 2 CTAs/SM.
template <bool POOL>
__global__ __launch_bounds__(288, 2) void conv14(int inb, int outb, int woff,
                                                 int prev, int wpar) {
    extern __shared__ float sm[];
    float* sI = sm;            // 12800
    float* sW = sm + 12800;    // 14400
    __shared__ double sSum[CF], sSq[CF];
    __shared__ float sSc[CF], sSh[CF];
    int tid = threadIdx.x, b = blockIdx.x, bd = blockDim.x;
    if (tid < CF) {
        sSum[tid] = 0.0; sSq[tid] = 0.0;
        sSc[tid] = g_scale[prev][tid]; sSh[tid] = g_shift[prev][tid];
    }
    float4* z4 = (float4*)sI;
    for (int i = tid; i < 3200; i += bd) z4[i] = make_float4(0.f, 0.f, 0.f, 0.f);
    __syncthreads();
    const float* srcbuf = (inb ? g_bufB : g_bufA);
    if (POOL) {
        for (int i = tid; i < 7840; i += bd) {
            int c = i / 196; int rem = i - c * 196; int py = rem / 14; int px = rem - py * 14;
            int f = c >> 2; float sc = sSc[f], sh = sSh[f];
            const float2* p0 = (const float2*)(srcbuf + b * 31360 + c * 784 + (py * 2) * 28 + px * 2);
            float2 u = p0[0], d = p0[14];
            float a0 = fmaxf(fmaf(u.x, sc, sh), 0.f);
            float a1 = fmaxf(fmaf(u.y, sc, sh), 0.f);
            float a2 = fmaxf(fmaf(d.x, sc, sh), 0.f);
            float a3 = fmaxf(fmaf(d.y, sc, sh), 0.f);
            sI[c * 320 + (py + 1) * 20 + px + 1] = fmaxf(fmaxf(a0, a1), fmaxf(a2, a3));
        }
    } else {
        for (int i4 = tid; i4 < 1960; i4 += bd) {
            int c = i4 / 49; int rem = i4 - c * 49;
            float4 v = *(const float4*)(srcbuf + b * 7840 + i4 * 4);
            int pos = rem * 4; int py = pos / 14; int px = pos - py * 14;
            int f = c >> 2; float sc = sSc[f], sh = sSh[f];
            float vv[4] = {v.x, v.y, v.z, v.w};
            float* base = sI + c * 320;
            #pragma unroll
            for (int j = 0; j < 4; j++) {
                base[(py + 1) * 20 + px + 1] = fmaxf(fmaf(vv[j], sc, sh), 0.f);
                if (++px == 14) { px = 0; py++; }
            }
        }
    }
    {
        const float4* wsrc = (const float4*)(g_wx + woff);
        float4* wdst = (float4*)sW;
        for (int i = tid; i < 3600; i += bd) wdst[i] = wsrc[i];
    }
    __syncthreads();
    float* dst = (outb ? g_bufB : g_bufA);
    {
        int item = tid; bool on = item < 280; int it = on ? item : 279;
        int chunk = it / 14; int y = it - chunk * 14; int cob = chunk * 2;
        ull acc2[14];
        #pragma unroll
        for (int p = 0; p < 14; p++) acc2[p] = 0ull;
        for (int ci = 0; ci < 40; ci++) {
            const float* Ir = sI + ci * 320 + y * 20;
            const float* wp = sW + ci * 360 + cob;
            #pragma unroll
            for (int ky = 0; ky < 3; ky++) {
                float4 v0 = *(const float4*)(Ir + ky * 20);
                float4 v1 = *(const float4*)(Ir + ky * 20 + 4);
                float4 v2 = *(const float4*)(Ir + ky * 20 + 8);
                float4 v3 = *(const float4*)(Ir + ky * 20 + 12);
                ull S[16];
                S[0]  = splat2(v0.x); S[1]  = splat2(v0.y); S[2]  = splat2(v0.z); S[3]  = splat2(v0.w);
                S[4]  = splat2(v1.x); S[5]  = splat2(v1.y); S[6]  = splat2(v1.z); S[7]  = splat2(v1.w);
                S[8]  = splat2(v2.x); S[9]  = splat2(v2.y); S[10] = splat2(v2.z); S[11] = splat2(v2.w);
                S[12] = splat2(v3.x); S[13] = splat2(v3.y); S[14] = splat2(v3.z); S[15] = splat2(v3.w);
                #pragma unroll
                for (int kx = 0; kx < 3; kx++) {
                    ull wv = *(const ull*)(wp + (ky * 3 + kx) * 40);
                    #pragma unroll
                    for (int p = 0; p < 14; p++) ffma2(acc2[p], S[p + kx], wv);
                }
            }
        }
        float s0 = 0, q0 = 0;
        if (on) {
            float* op0 = dst + ((b * 40 + cob) * 14 + y) * 14;
            float* op1 = op0 + 196;
            #pragma unroll
            for (int p = 0; p < 14; p++) {
                float a, bb; unpack2(acc2[p], a, bb);
                op0[p] = a; op1[p] = bb;
                s0 += a + bb; q0 += a * a + bb * bb;
            }
        }
        stat_flush1(chunk >> 1, s0, q0, sSum, sSq);
    }
    __syncthreads();
    if (tid < CF) {
        g_part[wpar][b * 20 + tid * 2]     = (float)sSum[tid];
        g_part[wpar][b * 20 + tid * 2 + 1] = (float)sSq[tid];
    }
}

// ---------------- layer 7: gconv 4x4, VALID, 14->11, two images per CTA ----------------
// FFMA2: 1 cout-pair x 11 px per thread, 448 threads.
__global__ __launch_bounds__(448) void conv4k(int inb, int outb, int woff,
                                              int prev, int wpar) {
    extern __shared__ float sm[];
    float* sI = sm;            // 22400
    float* sW = sm + 22400;    // 25600
    __shared__ double sSum[CF], sSq[CF];
    __shared__ float sSc[CF], sSh[CF];
    int tid = threadIdx.x, bd = blockDim.x;
    int b0 = blockIdx.x * 2;
    if (tid < CF) {
        sSum[tid] = 0.0; sSq[tid] = 0.0;
        sSc[tid] = g_scale[prev][tid]; sSh[tid] = g_shift[prev][tid];
    }
    __syncthreads();
    const float* srcbuf = (inb ? g_bufB : g_bufA);
    for (int i4 = tid; i4 < 3920; i4 += bd) {
        int img = i4 / 1960; int j4 = i4 - img * 1960;
        int c = j4 / 49; int rem = j4 - c * 49;
        float4 v = *(const float4*)(srcbuf + (b0 + img) * 7840 + j4 * 4);
        int pos = rem * 4; int py = pos / 14; int px = pos - py * 14;
        int f = c >> 2; float sc = sSc[f], sh = sSh[f];
        float vv[4] = {v.x, v.y, v.z, v.w};
        float* base = sI + (img * 40 + c) * 280;
        #pragma unroll
        for (int j = 0; j < 4; j++) {
            base[py * 20 + px] = fmaxf(fmaf(vv[j], sc, sh), 0.f);
            if (++px == 14) { px = 0; py++; }
        }
    }
    {
        const float4* wsrc = (const float4*)(g_wx + woff);
        float4* wdst = (float4*)sW;
        for (int i = tid; i < 6400; i += bd) wdst[i] = wsrc[i];
    }
    __syncthreads();
    float* dst = (outb ? g_bufB : g_bufA);
    {
        int item = tid; bool on = item < 440; int it = on ? item : 439;
        int img = it / 220; int rest = it - img * 220;
        int chunk = rest / 11; int y = rest - chunk * 11; int cob = chunk * 2;
        ull acc2[11];
        #pragma unroll
        for (int p = 0; p < 11; p++) acc2[p] = 0ull;
        for (int ci = 0; ci < 40; ci++) {
            const float* Ir = sI + (img * 40 + ci) * 280 + y * 20;
            const float* wp = sW + ci * 640 + cob;
            #pragma unroll
            for (int ky = 0; ky < 4; ky++) {
                float4 v0 = *(const float4*)(Ir + ky * 20);
                float4 v1 = *(const float4*)(Ir + ky * 20 + 4);
                float4 v2 = *(const float4*)(Ir + ky * 20 + 8);
                float2 v3 = *(const float2*)(Ir + ky * 20 + 12);
                ull S[14];
                S[0]  = splat2(v0.x); S[1]  = splat2(v0.y); S[2]  = splat2(v0.z); S[3]  = splat2(v0.w);
                S[4]  = splat2(v1.x); S[5]  = splat2(v1.y); S[6]  = splat2(v1.z); S[7]  = splat2(v1.w);
                S[8]  = splat2(v2.x); S[9]  = splat2(v2.y); S[10] = splat2(v2.z); S[11] = splat2(v2.w);
                S[12] = splat2(v3.x); S[13] = splat2(v3.y);
                #pragma unroll
                for (int kx = 0; kx < 4; kx++) {
                    ull wv = *(const ull*)(wp + (ky * 4 + kx) * 40);
                    #pragma unroll
                    for (int p = 0; p < 11; p++) ffma2(acc2[p], S[p + kx], wv);
                }
            }
        }
        float s0 = 0, q0 = 0;
        if (on) {
            float* op0 = dst + (((b0 + img) * 40 + cob) * 11 + y) * 11;
            float* op1 = op0 + 121;
            #pragma unroll
            for (int p = 0; p < 11; p++) {
                float a, bb; unpack2(acc2[p], a, bb);
                op0[p] = a; op1[p] = bb;
                s0 += a + bb; q0 += a * a + bb * bb;
            }
        }
        stat_flush1(chunk >> 1, s0, q0, sSum, sSq);
    }
    __syncthreads();
    if (tid < CF) {
        g_part[wpar][blockIdx.x * 20 + tid * 2]     = (float)sSum[tid];
        g_part[wpar][blockIdx.x * 20 + tid * 2 + 1] = (float)sSq[tid];
    }
}

// ---------------- act7 + orientation max + FC ----------------
__global__ __launch_bounds__(128) void fc_kernel(int inb, const float* __restrict__ wfc,
                                                 const float* __restrict__ bfc,
                                                 float* __restrict__ out, int prev) {
    __shared__ float sWf[12100];
    __shared__ float sOut[10];
    __shared__ float sSc[CF], sSh[CF];
    int tid = threadIdx.x, b = blockIdx.x;
    if (tid < 10) {
        sOut[tid] = bfc[tid];
        sSc[tid] = g_scale[prev][tid]; sSh[tid] = g_shift[prev][tid];
    }
    for (int i = tid; i < 12100; i += 128) sWf[i] = wfc[i];
    __syncthreads();
    const float* src = (inb ? g_bufB : g_bufA) + b * 4840;
    float acc[10];
    #pragma unroll
    for (int j = 0; j < 10; j++) acc[j] = 0.f;
    for (int idx = tid; idx < 1210; idx += 128) {
        int c = idx / 121; int p = idx - c * 121;
        const float* ip = src + c * 484 + p;
        float sc = sSc[c], sh = sSh[c];
        float a0 = fmaxf(fmaf(ip[0],   sc, sh), 0.f);
        float a1 = fmaxf(fmaf(ip[121], sc, sh), 0.f);
        float a2 = fmaxf(fmaf(ip[242], sc, sh), 0.f);
        float a3 = fmaxf(fmaf(ip[363], sc, sh), 0.f);
        float m = fmaxf(fmaxf(a0, a1), fmaxf(a2, a3));
        #pragma unroll
        for (int j = 0; j < 10; j++) acc[j] = fmaf(m, sWf[j * 1210 + idx], acc[j]);
    }
    #pragma unroll
    for (int j = 0; j < 10; j++) atomicAdd(&sOut[j], acc[j]);
    __syncthreads();
    if (tid < 10) out[b * 10 + tid] = sOut[tid];
}

// ---------------- launch ----------------
extern "C" void kernel_launch(void* const* d_in, const int* in_sizes, int n_in,
                              void* d_out, int out_size) {
    const float* x   = (const float*)d_in[0];
    const float* w1  = (const float*)d_in[1];
    const float* w2  = (const float*)d_in[2];
    const float* w3  = (const float*)d_in[3];
    const float* w4  = (const float*)d_in[4];
    const float* w5  = (const float*)d_in[5];
    const float* w6  = (const float*)d_in[6];
    const float* w7  = (const float*)d_in[7];
    const float* g1  = (const float*)d_in[8];
    const float* b1  = (const float*)d_in[9];
    const float* g2  = (const float*)d_in[10];
    const float* b2  = (const float*)d_in[11];
    const float* gs  = (const float*)d_in[12];
    const float* bs  = (const float*)d_in[13];
    const float* wfc = (const float*)d_in[14];
    const float* bfc = (const float*)d_in[15];
    float* out = (float*)d_out;

    const int SMEM28 = (20480 + 7200) * 4;    // 110720
    const int SMEM14 = (12800 + 14400) * 4;   // 108800
    const int SMEM4  = (22400 + 25600) * 4;   // 192000
    cudaFuncSetAttribute(conv28,        cudaFuncAttributeMaxDynamicSharedMemorySize, SMEM28);
    cudaFuncSetAttribute(conv14<true>,  cudaFuncAttributeMaxDynamicSharedMemorySize, SMEM14);
    cudaFuncSetAttribute(conv14<false>, cudaFuncAttributeMaxDynamicSharedMemorySize, SMEM14);
    cudaFuncSetAttribute(conv4k,        cudaFuncAttributeMaxDynamicSharedMemorySize, SMEM4);

    const double iN28 = 1.0 / (1024.0 * 4.0 * 784.0);
    const double iN14 = 1.0 / (1024.0 * 4.0 * 196.0);
    const double iN11 = 1.0 / (1024.0 * 4.0 * 121.0);

    expand_weights<<<383, 256>>>(w1, w2, w3, w4, w5, w6, w7);

    // layer L writes g_part[L & 1]; finalize_bn(L) reduces it into g_scale/g_shift[L]
    lift_conv<<<1024, 256>>>(x);                                    // -> A, part[0] (1024)
    finalize_bn<<<1, 320>>>(0, 0, 1024, g1, b1, iN28);
    conv28<<<4096, 256, SMEM28>>>(0, 1, WOFF_W2, 0, 1);             // A->B, part[1] (4096)
    finalize_bn<<<1, 320>>>(1, 1, 4096, g2, b2, iN28);
    conv14<true><<<1024, 288, SMEM14>>>(1, 0, WOFF_W3, 1, 0);       // pool(B)->A, part[0] (1024)
    finalize_bn<<<1, 320>>>(2, 0, 1024, gs, bs, iN14);
    conv14<false><<<1024, 288, SMEM14>>>(0, 1, WOFF_W4, 2, 1);      // A->B, part[1]
    finalize_bn<<<1, 320>>>(3, 1, 1024, gs, bs, iN14);
    conv14<false><<<1024, 288, SMEM14>>>(1, 0, WOFF_W5, 3, 0);      // B->A, part[0]
    finalize_bn<<<1, 320>>>(4, 0, 1024, gs, bs, iN14);
    conv14<false><<<1024, 288, SMEM14>>>(0, 1, WOFF_W6, 4, 1);      // A->B, part[1]
    finalize_bn<<<1, 320>>>(5, 1, 1024, gs, bs, iN14);
    conv4k<<<512, 448, SMEM4>>>(1, 0, WOFF_W7, 5, 0);               // B->A (11x11), part[0] (512)
    finalize_bn<<<1, 320>>>(6, 0, 512, gs, bs, iN11);
    fc_kernel<<<1024, 128>>>(0, wfc, bfc, out, 6);                  // A -> out
}